// round 3
// baseline (speedup 1.0000x reference)
#include <cuda_runtime.h>

// y = irfft2(rfft2(pad(u)) * rfft2(pad(k)), ortho) cropped.
// (4,64,251,509) fp32 -> 256 images 251x509, pad to 256x512.
// Trick: pack z = u + i*k; after full 2D FFT of z,
//   U2 = (Z2[ky,kx] + conj(Z2[-ky,-kx]))/2,  K2 = (Z2 - conj(Z2[-ky,-kx]))/(2i)
//   P  = U2*K2 = -0.25i * (Z2^2 - conj(Z2[-ky,-kx])^2)
// so no Hermitian split is ever materialized. Combined ortho scale 2^-25.5.

#define IMGS 256
#define HH   251
#define WW   509
#define NJ   257
#define ZP   516   // float2 row stride of full-width Z scratch
#define WPAD 260   // float2 row stride of product scratch
#define P512 72    // exchange-1 stride (conflict-free)
#define P512B 66   // exchange-2 m2-stride (conflict-free both sides)

__device__ float2 g_Z[IMGS * HH * ZP];     // packed row spectra -> product input
__device__ float2 g_P[IMGS * HH * WPAD];   // column-inverse product (half spectrum)
__device__ float2 g_tw[512];               // tw[r] = exp(-2*pi*i*r/512)

__global__ void init_tw_kernel() {
    int r = threadIdx.x;
    double ang = -2.0 * 3.141592653589793238462643383279502884 * (double)r / 512.0;
    g_tw[r] = make_float2((float)cos(ang), (float)sin(ang));
}

__device__ __forceinline__ float2 cmul(float2 a, float2 b) {
    return make_float2(a.x*b.x - a.y*b.y, a.x*b.y + a.y*b.x);
}
__device__ __forceinline__ float2 cadd(float2 a, float2 b) { return make_float2(a.x+b.x, a.y+b.y); }
__device__ __forceinline__ float2 csub(float2 a, float2 b) { return make_float2(a.x-b.x, a.y-b.y); }
template<int DIR>
__device__ __forceinline__ float2 mulmi(float2 v) {   // * (-i) fwd, * (+i) inv
    return (DIR == 1) ? make_float2(v.y, -v.x) : make_float2(-v.y, v.x);
}

template<int DIR>
__device__ __forceinline__ void dft8(float2 x[8]) {
    const float C = 0.70710678118654752f;
    float2 t0 = cadd(x[0], x[4]), t4 = csub(x[0], x[4]);
    float2 t1 = cadd(x[1], x[5]), t5 = csub(x[1], x[5]);
    float2 t2 = cadd(x[2], x[6]), t6 = csub(x[2], x[6]);
    float2 t3 = cadd(x[3], x[7]), t7 = csub(x[3], x[7]);
    t5 = cmul(t5, make_float2(C, -DIR * C));
    t6 = mulmi<DIR>(t6);
    t7 = cmul(t7, make_float2(-C, -DIR * C));
    float2 p0 = cadd(t0, t2), q0 = csub(t0, t2);
    float2 p1 = cadd(t1, t3), q1 = mulmi<DIR>(csub(t1, t3));
    x[0] = cadd(p0, p1); x[4] = csub(p0, p1);
    x[2] = cadd(q0, q1); x[6] = csub(q0, q1);
    float2 r0 = cadd(t4, t6), s0 = csub(t4, t6);
    float2 r1 = cadd(t5, t7), s1 = mulmi<DIR>(csub(t5, t7));
    x[1] = cadd(r0, r1); x[5] = csub(r0, r1);
    x[3] = cadd(s0, s1); x[7] = csub(s0, s1);
}

template<int DIR>
__device__ __forceinline__ void dft16(float2 x[16]) {
    float2 y[16];
#pragma unroll
    for (int b = 0; b < 4; b++) {
        float2 a0 = x[b], a1 = x[b + 4], a2 = x[b + 8], a3 = x[b + 12];
        float2 t0 = cadd(a0, a2), t1 = csub(a0, a2);
        float2 t2 = cadd(a1, a3), t3 = mulmi<DIR>(csub(a1, a3));
        y[b*4 + 0] = cadd(t0, t2);
        y[b*4 + 1] = cadd(t1, t3);
        y[b*4 + 2] = csub(t0, t2);
        y[b*4 + 3] = csub(t1, t3);
    }
    const float c1 = 0.9238795325112867f, s1 = 0.3826834323650898f;
    const float C = 0.70710678118654752f;
    const float2 w1 = make_float2(c1, -DIR * s1);
    const float2 w2 = make_float2(C, -DIR * C);
    const float2 w3 = make_float2(s1, -DIR * c1);
    const float2 w4 = make_float2(0.f, (float)(-DIR));
    const float2 w6 = make_float2(-C, -DIR * C);
    const float2 w9 = make_float2(-c1, DIR * s1);
    y[5]  = cmul(y[5],  w1); y[6]  = cmul(y[6],  w2); y[7]  = cmul(y[7],  w3);
    y[9]  = cmul(y[9],  w2); y[10] = cmul(y[10], w4); y[11] = cmul(y[11], w6);
    y[13] = cmul(y[13], w3); y[14] = cmul(y[14], w6); y[15] = cmul(y[15], w9);
#pragma unroll
    for (int k1 = 0; k1 < 4; k1++) {
        float2 a0 = y[k1], a1 = y[4 + k1], a2 = y[8 + k1], a3 = y[12 + k1];
        float2 t0 = cadd(a0, a2), t1 = csub(a0, a2);
        float2 t2 = cadd(a1, a3), t3 = mulmi<DIR>(csub(a1, a3));
        x[0*4 + k1] = cadd(t0, t2);
        x[1*4 + k1] = cadd(t1, t3);
        x[2*4 + k1] = csub(t0, t2);
        x[3*4 + k1] = csub(t1, t3);
    }
}

// FFT-512: 64 threads, x[n1] = x[n1*64+t] on entry, x[q2] = X[q2*64+t] on exit.
// Both smem exchanges bank-conflict-free per 16-lane phase. s: 576 float2.
template<int DIR>
__device__ __forceinline__ void fft512_core(float2 x[8], float2* s, int t) {
    dft8<DIR>(x);
    float2 w = g_tw[t];
    if (DIR < 0) w.y = -w.y;
    float2 cw = w;
#pragma unroll
    for (int k1 = 1; k1 < 8; k1++) { x[k1] = cmul(x[k1], cw); cw = cmul(cw, w); }
#pragma unroll
    for (int k1 = 0; k1 < 8; k1++) s[k1 * P512 + t] = x[k1];
    __syncthreads();
    int k1 = t >> 3, m2 = t & 7;
#pragma unroll
    for (int m1 = 0; m1 < 8; m1++) x[m1] = s[k1 * P512 + m1 * 8 + m2];
    __syncthreads();
    dft8<DIR>(x);
    w = g_tw[8 * m2];
    if (DIR < 0) w.y = -w.y;
    cw = w;
#pragma unroll
    for (int q1 = 1; q1 < 8; q1++) { x[q1] = cmul(x[q1], cw); cw = cmul(cw, w); }
#pragma unroll
    for (int q1 = 0; q1 < 8; q1++) s[m2 * P512B + q1 * 8 + k1] = x[q1];
    __syncthreads();
    int k1c = t & 7, q1c = t >> 3;
#pragma unroll
    for (int m = 0; m < 8; m++) x[m] = s[m * P512B + q1c * 8 + k1c];
    __syncthreads();
    dft8<DIR>(x);   // output: X[q2*64 + q1c*8 + k1c] = X[q2*64 + t]
}

// FFT-256: 16 threads/column (role q), column c. Entry x[n1]=x[n1*16+q],
// exit x[k2]=X[k2*16+q]. E: 16x272 float2 exchange region.
template<int DIR>
__device__ __forceinline__ void fft256_core(float2 x[16], float2* E, int c, int q) {
    dft16<DIR>(x);
    float2 w = g_tw[2 * q];
    if (DIR < 0) w.y = -w.y;
    float2 cw = w;
#pragma unroll
    for (int k1 = 1; k1 < 16; k1++) { x[k1] = cmul(x[k1], cw); cw = cmul(cw, w); }
#pragma unroll
    for (int k1 = 0; k1 < 16; k1++) E[c * 272 + k1 * 17 + q] = x[k1];
    __syncthreads();
#pragma unroll
    for (int n2 = 0; n2 < 16; n2++) x[n2] = E[c * 272 + q * 17 + n2];
    __syncthreads();
    dft16<DIR>(x);
}

// Stage 1: per row: pack z=u+ik, FFT-512 fwd, store full raw spectrum.
__global__ void __launch_bounds__(256) stage1_kernel(const float* __restrict__ u,
                                                     const float* __restrict__ kin) {
    __shared__ float2 sm[4][576];
    int t = threadIdx.x & 63;
    int r = threadIdx.x >> 6;
    int row = blockIdx.x * 4 + r;       // img*251 + h
    size_t ibase = (size_t)row * WW;
    float2 x[8];
#pragma unroll
    for (int a = 0; a < 8; a++) {
        int n = a * 64 + t;
        float ur = 0.f, kr = 0.f;
        if (n < WW) { ur = u[ibase + n]; kr = kin[ibase + n]; }
        x[a] = make_float2(ur, kr);
    }
    fft512_core<1>(x, sm[r], t);
    size_t obase = (size_t)row * ZP;
#pragma unroll
    for (int q2 = 0; q2 < 8; q2++) g_Z[obase + q2 * 64 + t] = x[q2];
}

// Stage 2: per (image, 16-col tile): column-FFT the mirror tile, shuffle-gather
// conj(Z2[-ky, mirror-col]); column-FFT the primary tile; product
// P = -0.25i*(A^2 - Bbar^2) with combined ortho scale; inverse column FFT;
// write half-spectrum product to g_P.
__global__ void __launch_bounds__(256, 2) stage2_kernel() {
    __shared__ float2 A[4352];   // 16x272 exchange / 256x17 staging
    const int t = threadIdx.x;
    const int c = t >> 4;     // FFT column role / staging row sub-index
    const int q = t & 15;     // within-column FFT role / staging column
    const int img = blockIdx.y;
    const int j0  = blockIdx.x * 16;
    const size_t zbase = (size_t)img * HH * ZP;
    float2 zv = make_float2(0.f, 0.f);

    // ---- stage + FFT mirror tile: col (512 - (j0+q)) & 511 ----
    int jm = (512 - (j0 + q)) & 511;
#pragma unroll
    for (int m = 0; m < 16; m++) {
        int h = c + 16 * m;
        A[h * 17 + q] = (h < HH) ? g_Z[zbase + (size_t)h * ZP + jm] : zv;
    }
    __syncthreads();
    float2 xm[16];
#pragma unroll
    for (int n1 = 0; n1 < 16; n1++) xm[n1] = A[(n1 * 16 + q) * 17 + c];
    __syncthreads();
    fft256_core<1>(xm, A, c, q);

    // ---- gather Bbar[k2] = conj(Zm2[(256 - (k2*16+q)) % 256]) via shuffles ----
    float2 bm[16];
    {
        int lane = t & 31;
        int src = (lane & 16) | ((16 - q) & 15);
#pragma unroll
        for (int k2 = 0; k2 < 16; k2++) {
            float2 v;
            v.x = __shfl_sync(0xffffffffu, xm[15 - k2].x, src);
            v.y = __shfl_sync(0xffffffffu, xm[15 - k2].y, src);
            if (q == 0) v = xm[(16 - k2) & 15];
            bm[k2] = make_float2(v.x, -v.y);
        }
    }

    // ---- stage + FFT primary tile: col j0+q ----
#pragma unroll
    for (int m = 0; m < 16; m++) {
        int h = c + 16 * m;
        A[h * 17 + q] = (h < HH) ? g_Z[zbase + (size_t)h * ZP + j0 + q] : zv;
    }
    __syncthreads();
    float2 xp[16];
#pragma unroll
    for (int n1 = 0; n1 < 16; n1++) xp[n1] = A[(n1 * 16 + q) * 17 + c];
    __syncthreads();
    fft256_core<1>(xp, A, c, q);

    // ---- product: P = (A+Bbar)(A-Bbar) * (-0.25i * 2^-25.5) ----
    const float CS = 0.25f * 2.1073424255447017e-08f;
#pragma unroll
    for (int k2 = 0; k2 < 16; k2++) {
        float2 s1 = cadd(xp[k2], bm[k2]);
        float2 s2 = csub(xp[k2], bm[k2]);
        float2 pr = cmul(s1, s2);
        xp[k2] = make_float2(CS * pr.y, -CS * pr.x);
    }

    // ---- inverse column FFT ----
    fft256_core<-1>(xp, A, c, q);

    // ---- stage out (coalesced half-spectrum writes) ----
#pragma unroll
    for (int k2 = 0; k2 < 16; k2++) A[(k2 * 16 + q) * 17 + c] = xp[k2];
    __syncthreads();
    if (j0 + q < NJ) {
        size_t pbase = (size_t)img * HH * WPAD + j0 + q;
#pragma unroll
        for (int m = 0; m < 16; m++) {
            int h = c + 16 * m;
            if (h < HH) g_P[pbase + (size_t)h * WPAD] = A[h * 17 + q];
        }
    }
}

// Stage 3: per output row: registers loaded straight from global with
// Hermitian mirror (no smem staging), inverse FFT-512, write real part.
__global__ void __launch_bounds__(256) stage3_kernel(float* __restrict__ out) {
    __shared__ float2 sm[4][576];
    int t = threadIdx.x & 63;
    int r = threadIdx.x >> 6;
    int row = blockIdx.x * 4 + r;
    size_t ibase = (size_t)row * WPAD;
    float2 x[8];
#pragma unroll
    for (int a = 0; a < 8; a++) {
        int n = a * 64 + t;
        if (n <= 256) {
            x[a] = g_P[ibase + n];
        } else {
            float2 v = g_P[ibase + 512 - n];
            x[a] = make_float2(v.x, -v.y);
        }
    }
    fft512_core<-1>(x, sm[r], t);
    size_t obase = (size_t)row * WW;
#pragma unroll
    for (int q2 = 0; q2 < 8; q2++) {
        int n = q2 * 64 + t;
        if (n < WW) out[obase + n] = x[q2].x;
    }
}

extern "C" void kernel_launch(void* const* d_in, const int* in_sizes, int n_in,
                              void* d_out, int out_size) {
    const float* u  = (const float*)d_in[0];
    const float* kk = (const float*)d_in[1];
    float* out = (float*)d_out;

    init_tw_kernel<<<1, 512>>>();
    stage1_kernel<<<16064, 256>>>(u, kk);            // 64256 rows / 4
    stage2_kernel<<<dim3(17, IMGS), 256>>>();        // 17 col-tiles x 256 images
    stage3_kernel<<<16064, 256>>>(out);
}

// round 4
// speedup vs baseline: 1.3122x; 1.3122x over previous
#include <cuda_runtime.h>

// y = irfft2(rfft2(pad(u)) * rfft2(pad(k)), ortho) cropped.
// (4,64,251,509) fp32 -> 256 images 251x509, pad to 256x512.
// Pack z = u + i*k; with Z2 = FFT2(z):
//   P = U2*K2 = -0.25i*(Z2[ky,kx]^2 - conj(Z2[-ky,-kx])^2)
// and conj(Z2[-ky,-kx]) = FFT_col(conj(Z[h,-kx])) -- conj-on-load, no gather.
// Combined ortho scale 2^-25.5 folded into the product.

#define IMGS 256
#define HH   251
#define WW   509
#define NJ   257
#define ZP   516   // float2 row stride of full-width Z scratch
#define WPAD 260   // float2 row stride of product scratch
#define EX1S 10    // exchange-1 thread-major stride (16B aligned, conflict-free)
#define P512B 66   // exchange-2 m2-stride (conflict-free both sides)
#define SROW 656   // per-row smem floats2 for fft512 (>= 64*10)

__device__ float2 g_Z[IMGS * HH * ZP];     // packed row spectra
__device__ float2 g_P[IMGS * HH * WPAD];   // column-inverse product (half spectrum)
__device__ float2 g_tw[512];               // tw[r] = exp(-2*pi*i*r/512)

__global__ void init_tw_kernel() {
    int r = threadIdx.x;
    double ang = -2.0 * 3.141592653589793238462643383279502884 * (double)r / 512.0;
    g_tw[r] = make_float2((float)cos(ang), (float)sin(ang));
}

__device__ __forceinline__ float2 cmul(float2 a, float2 b) {
    return make_float2(a.x*b.x - a.y*b.y, a.x*b.y + a.y*b.x);
}
__device__ __forceinline__ float2 cadd(float2 a, float2 b) { return make_float2(a.x+b.x, a.y+b.y); }
__device__ __forceinline__ float2 csub(float2 a, float2 b) { return make_float2(a.x-b.x, a.y-b.y); }
template<int DIR>
__device__ __forceinline__ float2 mulmi(float2 v) {   // * (-i) fwd, * (+i) inv
    return (DIR == 1) ? make_float2(v.y, -v.x) : make_float2(-v.y, v.x);
}

#define BAR64(id) asm volatile("bar.sync %0, 64;" :: "r"(id) : "memory")

template<int DIR>
__device__ __forceinline__ void dft8(float2 x[8]) {
    const float C = 0.70710678118654752f;
    float2 t0 = cadd(x[0], x[4]), t4 = csub(x[0], x[4]);
    float2 t1 = cadd(x[1], x[5]), t5 = csub(x[1], x[5]);
    float2 t2 = cadd(x[2], x[6]), t6 = csub(x[2], x[6]);
    float2 t3 = cadd(x[3], x[7]), t7 = csub(x[3], x[7]);
    t5 = cmul(t5, make_float2(C, -DIR * C));
    t6 = mulmi<DIR>(t6);
    t7 = cmul(t7, make_float2(-C, -DIR * C));
    float2 p0 = cadd(t0, t2), q0 = csub(t0, t2);
    float2 p1 = cadd(t1, t3), q1 = mulmi<DIR>(csub(t1, t3));
    x[0] = cadd(p0, p1); x[4] = csub(p0, p1);
    x[2] = cadd(q0, q1); x[6] = csub(q0, q1);
    float2 r0 = cadd(t4, t6), s0 = csub(t4, t6);
    float2 r1 = cadd(t5, t7), s1 = mulmi<DIR>(csub(t5, t7));
    x[1] = cadd(r0, r1); x[5] = csub(r0, r1);
    x[3] = cadd(s0, s1); x[7] = csub(s0, s1);
}

template<int DIR>
__device__ __forceinline__ void dft16(float2 x[16]) {
    float2 y[16];
#pragma unroll
    for (int b = 0; b < 4; b++) {
        float2 a0 = x[b], a1 = x[b + 4], a2 = x[b + 8], a3 = x[b + 12];
        float2 t0 = cadd(a0, a2), t1 = csub(a0, a2);
        float2 t2 = cadd(a1, a3), t3 = mulmi<DIR>(csub(a1, a3));
        y[b*4 + 0] = cadd(t0, t2);
        y[b*4 + 1] = cadd(t1, t3);
        y[b*4 + 2] = csub(t0, t2);
        y[b*4 + 3] = csub(t1, t3);
    }
    const float c1 = 0.9238795325112867f, s1 = 0.3826834323650898f;
    const float C = 0.70710678118654752f;
    const float2 w1 = make_float2(c1, -DIR * s1);
    const float2 w2 = make_float2(C, -DIR * C);
    const float2 w3 = make_float2(s1, -DIR * c1);
    const float2 w4 = make_float2(0.f, (float)(-DIR));
    const float2 w6 = make_float2(-C, -DIR * C);
    const float2 w9 = make_float2(-c1, DIR * s1);
    y[5]  = cmul(y[5],  w1); y[6]  = cmul(y[6],  w2); y[7]  = cmul(y[7],  w3);
    y[9]  = cmul(y[9],  w2); y[10] = cmul(y[10], w4); y[11] = cmul(y[11], w6);
    y[13] = cmul(y[13], w3); y[14] = cmul(y[14], w6); y[15] = cmul(y[15], w9);
#pragma unroll
    for (int k1 = 0; k1 < 4; k1++) {
        float2 a0 = y[k1], a1 = y[4 + k1], a2 = y[8 + k1], a3 = y[12 + k1];
        float2 t0 = cadd(a0, a2), t1 = csub(a0, a2);
        float2 t2 = cadd(a1, a3), t3 = mulmi<DIR>(csub(a1, a3));
        x[0*4 + k1] = cadd(t0, t2);
        x[1*4 + k1] = cadd(t1, t3);
        x[2*4 + k1] = csub(t0, t2);
        x[3*4 + k1] = csub(t1, t3);
    }
}

// FFT-512: 64 threads, x[n1] = x[n1*64+t] on entry, x[q2] = X[q2*64+t] on exit.
// Exchange-1 stores are float4-vectorized (thread-major, stride 10); all smem
// phases bank-conflict-free. Synced with per-row named barriers (bar id).
template<int DIR>
__device__ __forceinline__ void fft512_core(float2 x[8], float2* s, int t, int bid) {
    dft8<DIR>(x);
    float2 w = g_tw[t];
    if (DIR < 0) w.y = -w.y;
    float2 cw = w;
#pragma unroll
    for (int k1 = 1; k1 < 8; k1++) { x[k1] = cmul(x[k1], cw); cw = cmul(cw, w); }
    {
        float4* s4 = reinterpret_cast<float4*>(s + (size_t)t * EX1S);
        s4[0] = make_float4(x[0].x, x[0].y, x[1].x, x[1].y);
        s4[1] = make_float4(x[2].x, x[2].y, x[3].x, x[3].y);
        s4[2] = make_float4(x[4].x, x[4].y, x[5].x, x[5].y);
        s4[3] = make_float4(x[6].x, x[6].y, x[7].x, x[7].y);
    }
    BAR64(bid);
    int k1 = t >> 3, m2 = t & 7;
#pragma unroll
    for (int m1 = 0; m1 < 8; m1++) x[m1] = s[(m1 * 8 + m2) * EX1S + k1];
    BAR64(bid);
    dft8<DIR>(x);
    w = g_tw[8 * m2];
    if (DIR < 0) w.y = -w.y;
    cw = w;
#pragma unroll
    for (int q1 = 1; q1 < 8; q1++) { x[q1] = cmul(x[q1], cw); cw = cmul(cw, w); }
#pragma unroll
    for (int q1 = 0; q1 < 8; q1++) s[m2 * P512B + q1 * 8 + k1] = x[q1];
    BAR64(bid);
    int k1c = t & 7, q1c = t >> 3;
#pragma unroll
    for (int m = 0; m < 8; m++) x[m] = s[m * P512B + q1c * 8 + k1c];
    BAR64(bid);
    dft8<DIR>(x);   // output: X[q2*64 + q1c*8 + k1c] = X[q2*64 + t]
}

// FFT-256: 16 threads/column (role q), column c. Entry x[n1]=x[n1*16+q],
// exit x[k2]=X[k2*16+q]. Exchange region is per-half-warp -> __syncwarp only.
template<int DIR>
__device__ __forceinline__ void fft256_core(float2 x[16], float2* E, int c, int q) {
    dft16<DIR>(x);
    float2 w = g_tw[2 * q];
    if (DIR < 0) w.y = -w.y;
    float2 cw = w;
#pragma unroll
    for (int k1 = 1; k1 < 16; k1++) { x[k1] = cmul(x[k1], cw); cw = cmul(cw, w); }
#pragma unroll
    for (int k1 = 0; k1 < 16; k1++) E[c * 272 + k1 * 17 + q] = x[k1];
    __syncwarp();
#pragma unroll
    for (int n2 = 0; n2 < 16; n2++) x[n2] = E[c * 272 + q * 17 + n2];
    __syncwarp();
    dft16<DIR>(x);
}

// Stage 1: per row: pack z=u+ik, FFT-512 fwd, store full raw spectrum.
__global__ void __launch_bounds__(256) stage1_kernel(const float* __restrict__ u,
                                                     const float* __restrict__ kin) {
    __shared__ __align__(16) float2 sm[4][SROW];
    int t = threadIdx.x & 63;
    int r = threadIdx.x >> 6;
    int row = blockIdx.x * 4 + r;       // img*251 + h
    size_t ibase = (size_t)row * WW;
    float2 x[8];
#pragma unroll
    for (int a = 0; a < 8; a++) {
        int n = a * 64 + t;
        float ur = 0.f, kr = 0.f;
        if (n < WW) { ur = u[ibase + n]; kr = kin[ibase + n]; }
        x[a] = make_float2(ur, kr);
    }
    fft512_core<1>(x, sm[r], t, r + 1);
    size_t obase = (size_t)row * ZP;
#pragma unroll
    for (int q2 = 0; q2 < 8; q2++) g_Z[obase + q2 * 64 + t] = x[q2];
}

// Stage 2: per (image, 16-col tile):
//   fwd FFT-256 of conj(mirror columns)  -> Bbar directly in place
//   term2 = +CS*i*Bbar^2  -> smem T2 (frees all registers)
//   fwd FFT-256 of primary columns       -> A2
//   product x = -CS*i*A2^2 + term2 ; inverse FFT-256 ; write half spectrum.
__global__ void __launch_bounds__(256, 2) stage2_kernel() {
    extern __shared__ float2 dsm[];
    float2* A  = dsm;          // 4352: staging (256x17) / exchange (16x272)
    float2* T2 = dsm + 4352;   // 4096: 16 cols x 256 rows
    const int t = threadIdx.x;
    const int c = t >> 4;
    const int q = t & 15;
    const int img = blockIdx.y;
    const int j0  = blockIdx.x * 16;
    const size_t zbase = (size_t)img * HH * ZP;
    const float CS = 0.25f * 2.1073424255447017e-08f;  // 0.25 * 2^-25.5
    float2 zv = make_float2(0.f, 0.f);
    float2 x[16];

    // ---- mirror tile, conjugated on load ----
    int jm = (512 - (j0 + q)) & 511;
#pragma unroll
    for (int m = 0; m < 16; m++) {
        int h = c + 16 * m;
        float2 v = (h < HH) ? g_Z[zbase + (size_t)h * ZP + jm] : zv;
        A[h * 17 + q] = make_float2(v.x, -v.y);
    }
    __syncthreads();
#pragma unroll
    for (int n1 = 0; n1 < 16; n1++) x[n1] = A[(n1 * 16 + q) * 17 + c];
    __syncthreads();
    fft256_core<1>(x, A, c, q);          // x[k2] = conj(Z2[-ky, -(j0+c)])

    // term2 = +CS * i * Bbar^2
#pragma unroll
    for (int k2 = 0; k2 < 16; k2++) {
        float2 pr = cmul(x[k2], x[k2]);
        T2[c * 256 + k2 * 16 + q] = make_float2(-CS * pr.y, CS * pr.x);
    }
    __syncthreads();

    // ---- primary tile ----
#pragma unroll
    for (int m = 0; m < 16; m++) {
        int h = c + 16 * m;
        A[h * 17 + q] = (h < HH) ? g_Z[zbase + (size_t)h * ZP + j0 + q] : zv;
    }
    __syncthreads();
#pragma unroll
    for (int n1 = 0; n1 < 16; n1++) x[n1] = A[(n1 * 16 + q) * 17 + c];
    __syncthreads();
    fft256_core<1>(x, A, c, q);          // x[k2] = Z2[ky, j0+c]

    // ---- product: x = -CS*i*A2^2 + term2 ----
#pragma unroll
    for (int k2 = 0; k2 < 16; k2++) {
        float2 pr = cmul(x[k2], x[k2]);
        float2 t2 = T2[c * 256 + k2 * 16 + q];
        x[k2] = make_float2(CS * pr.y + t2.x, -CS * pr.x + t2.y);
    }

    // ---- inverse column FFT ----
    fft256_core<-1>(x, A, c, q);

    // ---- stage out (coalesced half-spectrum writes) ----
    __syncthreads();
#pragma unroll
    for (int k2 = 0; k2 < 16; k2++) A[(k2 * 16 + q) * 17 + c] = x[k2];
    __syncthreads();
    if (j0 + q < NJ) {
        size_t pbase = (size_t)img * HH * WPAD + j0 + q;
#pragma unroll
        for (int m = 0; m < 16; m++) {
            int h = c + 16 * m;
            if (h < HH) g_P[pbase + (size_t)h * WPAD] = A[h * 17 + q];
        }
    }
}

// Stage 3: per output row: registers loaded straight from global with
// Hermitian mirror, inverse FFT-512, write real part of 509 samples.
__global__ void __launch_bounds__(256) stage3_kernel(float* __restrict__ out) {
    __shared__ __align__(16) float2 sm[4][SROW];
    int t = threadIdx.x & 63;
    int r = threadIdx.x >> 6;
    int row = blockIdx.x * 4 + r;
    size_t ibase = (size_t)row * WPAD;
    float2 x[8];
#pragma unroll
    for (int a = 0; a < 8; a++) {
        int n = a * 64 + t;
        if (n <= 256) {
            x[a] = g_P[ibase + n];
        } else {
            float2 v = g_P[ibase + 512 - n];
            x[a] = make_float2(v.x, -v.y);
        }
    }
    fft512_core<-1>(x, sm[r], t, r + 1);
    size_t obase = (size_t)row * WW;
#pragma unroll
    for (int q2 = 0; q2 < 8; q2++) {
        int n = q2 * 64 + t;
        if (n < WW) out[obase + n] = x[q2].x;
    }
}

extern "C" void kernel_launch(void* const* d_in, const int* in_sizes, int n_in,
                              void* d_out, int out_size) {
    const float* u  = (const float*)d_in[0];
    const float* kk = (const float*)d_in[1];
    float* out = (float*)d_out;

    cudaFuncSetAttribute(stage2_kernel,
                         cudaFuncAttributeMaxDynamicSharedMemorySize, 67584);

    init_tw_kernel<<<1, 512>>>();
    stage1_kernel<<<16064, 256>>>(u, kk);            // 64256 rows / 4
    stage2_kernel<<<dim3(17, IMGS), 256, 67584>>>(); // 17 col-tiles x 256 images
    stage3_kernel<<<16064, 256>>>(out);
}

// round 5
// speedup vs baseline: 1.5216x; 1.1595x over previous
#include <cuda_runtime.h>
#include <cuda_fp16.h>

// y = irfft2(rfft2(pad(u)) * rfft2(pad(k)), ortho) cropped.
// (4,64,251,509) fp32 -> 256 images 251x509, pad to 256x512.
// Pack z = u + i*k; with Z2 = FFT2(z):
//   P = U2*K2 = -0.25i*(Z2[ky,kx]^2 - conj(Z2[-ky,-kx])^2)
// and conj(Z2[-ky,-kx]) = FFT_col(conj(Z[h,-kx])) -- conj-on-load, no gather.
// Combined ortho scale 2^-25.5 folded into the product.
// Row spectra g_Z stored in fp16 (half2): tolerance is 1e-3, values ~O(100).

#define IMGS 256
#define HH   251
#define WW   509
#define NJ   257
#define ZP   516   // half2 row stride of full-width Z scratch
#define WPAD 260   // float2 row stride of product scratch
#define EX1S 10    // exchange-1 thread-major stride (16B aligned, conflict-free)
#define P512B 66   // exchange-2 m2-stride (conflict-free both sides)
#define SROW 656   // per-row smem float2 for fft512 (>= 64*10)

__device__ __half2 g_Zh[IMGS * HH * ZP];   // packed row spectra (fp16)
__device__ float2  g_P[IMGS * HH * WPAD];  // column-inverse product (half spectrum)
__device__ float2  g_tw[512];              // tw[r] = exp(-2*pi*i*r/512)

__global__ void init_tw_kernel() {
    int r = threadIdx.x;
    double ang = -2.0 * 3.141592653589793238462643383279502884 * (double)r / 512.0;
    g_tw[r] = make_float2((float)cos(ang), (float)sin(ang));
}

__device__ __forceinline__ float2 cmul(float2 a, float2 b) {
    return make_float2(a.x*b.x - a.y*b.y, a.x*b.y + a.y*b.x);
}
__device__ __forceinline__ float2 cadd(float2 a, float2 b) { return make_float2(a.x+b.x, a.y+b.y); }
__device__ __forceinline__ float2 csub(float2 a, float2 b) { return make_float2(a.x-b.x, a.y-b.y); }
template<int DIR>
__device__ __forceinline__ float2 mulmi(float2 v) {   // * (-i) fwd, * (+i) inv
    return (DIR == 1) ? make_float2(v.y, -v.x) : make_float2(-v.y, v.x);
}

// Pairwise row barrier: 128 threads (2 rows), ids {0,1} -> 2 HW barriers per
// block -> 8 blocks/SM fit the 16-barrier pool (R4 used 5 ids -> occ cap).
#define BAR128(id) asm volatile("bar.sync %0, 128;" :: "r"(id) : "memory")

template<int DIR>
__device__ __forceinline__ void dft8(float2 x[8]) {
    const float C = 0.70710678118654752f;
    float2 t0 = cadd(x[0], x[4]), t4 = csub(x[0], x[4]);
    float2 t1 = cadd(x[1], x[5]), t5 = csub(x[1], x[5]);
    float2 t2 = cadd(x[2], x[6]), t6 = csub(x[2], x[6]);
    float2 t3 = cadd(x[3], x[7]), t7 = csub(x[3], x[7]);
    t5 = cmul(t5, make_float2(C, -DIR * C));
    t6 = mulmi<DIR>(t6);
    t7 = cmul(t7, make_float2(-C, -DIR * C));
    float2 p0 = cadd(t0, t2), q0 = csub(t0, t2);
    float2 p1 = cadd(t1, t3), q1 = mulmi<DIR>(csub(t1, t3));
    x[0] = cadd(p0, p1); x[4] = csub(p0, p1);
    x[2] = cadd(q0, q1); x[6] = csub(q0, q1);
    float2 r0 = cadd(t4, t6), s0 = csub(t4, t6);
    float2 r1 = cadd(t5, t7), s1 = mulmi<DIR>(csub(t5, t7));
    x[1] = cadd(r0, r1); x[5] = csub(r0, r1);
    x[3] = cadd(s0, s1); x[7] = csub(s0, s1);
}

template<int DIR>
__device__ __forceinline__ void dft16(float2 x[16]) {
    float2 y[16];
#pragma unroll
    for (int b = 0; b < 4; b++) {
        float2 a0 = x[b], a1 = x[b + 4], a2 = x[b + 8], a3 = x[b + 12];
        float2 t0 = cadd(a0, a2), t1 = csub(a0, a2);
        float2 t2 = cadd(a1, a3), t3 = mulmi<DIR>(csub(a1, a3));
        y[b*4 + 0] = cadd(t0, t2);
        y[b*4 + 1] = cadd(t1, t3);
        y[b*4 + 2] = csub(t0, t2);
        y[b*4 + 3] = csub(t1, t3);
    }
    const float c1 = 0.9238795325112867f, s1 = 0.3826834323650898f;
    const float C = 0.70710678118654752f;
    const float2 w1 = make_float2(c1, -DIR * s1);
    const float2 w2 = make_float2(C, -DIR * C);
    const float2 w3 = make_float2(s1, -DIR * c1);
    const float2 w4 = make_float2(0.f, (float)(-DIR));
    const float2 w6 = make_float2(-C, -DIR * C);
    const float2 w9 = make_float2(-c1, DIR * s1);
    y[5]  = cmul(y[5],  w1); y[6]  = cmul(y[6],  w2); y[7]  = cmul(y[7],  w3);
    y[9]  = cmul(y[9],  w2); y[10] = cmul(y[10], w4); y[11] = cmul(y[11], w6);
    y[13] = cmul(y[13], w3); y[14] = cmul(y[14], w6); y[15] = cmul(y[15], w9);
#pragma unroll
    for (int k1 = 0; k1 < 4; k1++) {
        float2 a0 = y[k1], a1 = y[4 + k1], a2 = y[8 + k1], a3 = y[12 + k1];
        float2 t0 = cadd(a0, a2), t1 = csub(a0, a2);
        float2 t2 = cadd(a1, a3), t3 = mulmi<DIR>(csub(a1, a3));
        x[0*4 + k1] = cadd(t0, t2);
        x[1*4 + k1] = cadd(t1, t3);
        x[2*4 + k1] = csub(t0, t2);
        x[3*4 + k1] = csub(t1, t3);
    }
}

// FFT-512: 64 threads, x[n1] = x[n1*64+t] on entry, x[q2] = X[q2*64+t] on exit.
// Exchange-1 stores float4-vectorized; all smem phases conflict-free.
// Synced with paired-row named barriers (bid in {0,1}).
template<int DIR>
__device__ __forceinline__ void fft512_core(float2 x[8], float2* s, int t, int bid) {
    dft8<DIR>(x);
    float2 w = g_tw[t];
    if (DIR < 0) w.y = -w.y;
    float2 cw = w;
#pragma unroll
    for (int k1 = 1; k1 < 8; k1++) { x[k1] = cmul(x[k1], cw); cw = cmul(cw, w); }
    {
        float4* s4 = reinterpret_cast<float4*>(s + (size_t)t * EX1S);
        s4[0] = make_float4(x[0].x, x[0].y, x[1].x, x[1].y);
        s4[1] = make_float4(x[2].x, x[2].y, x[3].x, x[3].y);
        s4[2] = make_float4(x[4].x, x[4].y, x[5].x, x[5].y);
        s4[3] = make_float4(x[6].x, x[6].y, x[7].x, x[7].y);
    }
    BAR128(bid);
    int k1 = t >> 3, m2 = t & 7;
#pragma unroll
    for (int m1 = 0; m1 < 8; m1++) x[m1] = s[(m1 * 8 + m2) * EX1S + k1];
    BAR128(bid);
    dft8<DIR>(x);
    w = g_tw[8 * m2];
    if (DIR < 0) w.y = -w.y;
    cw = w;
#pragma unroll
    for (int q1 = 1; q1 < 8; q1++) { x[q1] = cmul(x[q1], cw); cw = cmul(cw, w); }
#pragma unroll
    for (int q1 = 0; q1 < 8; q1++) s[m2 * P512B + q1 * 8 + k1] = x[q1];
    BAR128(bid);
    int k1c = t & 7, q1c = t >> 3;
#pragma unroll
    for (int m = 0; m < 8; m++) x[m] = s[m * P512B + q1c * 8 + k1c];
    BAR128(bid);
    dft8<DIR>(x);   // output: X[q2*64 + q1c*8 + k1c] = X[q2*64 + t]
}

// FFT-256: 16 threads/column (role q), column c. Entry x[n1]=x[n1*16+q],
// exit x[k2]=X[k2*16+q]. Exchange region is per-half-warp -> __syncwarp only.
template<int DIR>
__device__ __forceinline__ void fft256_core(float2 x[16], float2* E, int c, int q) {
    dft16<DIR>(x);
    float2 w = g_tw[2 * q];
    if (DIR < 0) w.y = -w.y;
    float2 cw = w;
#pragma unroll
    for (int k1 = 1; k1 < 16; k1++) { x[k1] = cmul(x[k1], cw); cw = cmul(cw, w); }
#pragma unroll
    for (int k1 = 0; k1 < 16; k1++) E[c * 272 + k1 * 17 + q] = x[k1];
    __syncwarp();
#pragma unroll
    for (int n2 = 0; n2 < 16; n2++) x[n2] = E[c * 272 + q * 17 + n2];
    __syncwarp();
    dft16<DIR>(x);
}

// Stage 1: per row: pack z=u+ik, FFT-512 fwd, store full raw spectrum (fp16).
__global__ void __launch_bounds__(256) stage1_kernel(const float* __restrict__ u,
                                                     const float* __restrict__ kin) {
    __shared__ __align__(16) float2 sm[4][SROW];
    int t = threadIdx.x & 63;
    int r = threadIdx.x >> 6;
    int row = blockIdx.x * 4 + r;       // img*251 + h
    size_t ibase = (size_t)row * WW;
    float2 x[8];
#pragma unroll
    for (int a = 0; a < 8; a++) {
        int n = a * 64 + t;
        float ur = 0.f, kr = 0.f;
        if (n < WW) { ur = u[ibase + n]; kr = kin[ibase + n]; }
        x[a] = make_float2(ur, kr);
    }
    fft512_core<1>(x, sm[r], t, r >> 1);
    size_t obase = (size_t)row * ZP;
#pragma unroll
    for (int q2 = 0; q2 < 8; q2++)
        g_Zh[obase + q2 * 64 + t] = __float22half2_rn(x[q2]);
}

// Stage 2: per (image, 16-col tile):
//   fwd FFT-256 of conj(mirror columns)  -> Bbar directly in place
//   term2 = +CS*i*Bbar^2  -> smem T2 (frees all registers)
//   fwd FFT-256 of primary columns       -> A2
//   product x = -CS*i*A2^2 + term2 ; inverse FFT-256 ; write half spectrum.
__global__ void __launch_bounds__(256, 2) stage2_kernel() {
    extern __shared__ float2 dsm[];
    float2* A  = dsm;          // 4352: staging (256x17) / exchange (16x272)
    float2* T2 = dsm + 4352;   // 4096: 16 cols x 256 rows
    const int t = threadIdx.x;
    const int c = t >> 4;
    const int q = t & 15;
    const int img = blockIdx.y;
    const int j0  = blockIdx.x * 16;
    const size_t zbase = (size_t)img * HH * ZP;
    const float CS = 0.25f * 2.1073424255447017e-08f;  // 0.25 * 2^-25.5
    float2 x[16];

    // ---- mirror tile, conjugated on load ----
    int jm = (512 - (j0 + q)) & 511;
#pragma unroll
    for (int m = 0; m < 16; m++) {
        int h = c + 16 * m;
        float2 v = make_float2(0.f, 0.f);
        if (h < HH) v = __half22float2(g_Zh[zbase + (size_t)h * ZP + jm]);
        A[h * 17 + q] = make_float2(v.x, -v.y);
    }
    __syncthreads();
#pragma unroll
    for (int n1 = 0; n1 < 16; n1++) x[n1] = A[(n1 * 16 + q) * 17 + c];
    __syncthreads();
    fft256_core<1>(x, A, c, q);          // x[k2] = conj(Z2[-ky, -(j0+c)])

    // term2 = +CS * i * Bbar^2
#pragma unroll
    for (int k2 = 0; k2 < 16; k2++) {
        float2 pr = cmul(x[k2], x[k2]);
        T2[c * 256 + k2 * 16 + q] = make_float2(-CS * pr.y, CS * pr.x);
    }
    __syncthreads();

    // ---- primary tile ----
#pragma unroll
    for (int m = 0; m < 16; m++) {
        int h = c + 16 * m;
        float2 v = make_float2(0.f, 0.f);
        if (h < HH) v = __half22float2(g_Zh[zbase + (size_t)h * ZP + j0 + q]);
        A[h * 17 + q] = v;
    }
    __syncthreads();
#pragma unroll
    for (int n1 = 0; n1 < 16; n1++) x[n1] = A[(n1 * 16 + q) * 17 + c];
    __syncthreads();
    fft256_core<1>(x, A, c, q);          // x[k2] = Z2[ky, j0+c]

    // ---- product: x = -CS*i*A2^2 + term2 ----
#pragma unroll
    for (int k2 = 0; k2 < 16; k2++) {
        float2 pr = cmul(x[k2], x[k2]);
        float2 t2 = T2[c * 256 + k2 * 16 + q];
        x[k2] = make_float2(CS * pr.y + t2.x, -CS * pr.x + t2.y);
    }

    // ---- inverse column FFT ----
    fft256_core<-1>(x, A, c, q);

    // ---- stage out (coalesced half-spectrum writes) ----
    __syncthreads();
#pragma unroll
    for (int k2 = 0; k2 < 16; k2++) A[(k2 * 16 + q) * 17 + c] = x[k2];
    __syncthreads();
    if (j0 + q < NJ) {
        size_t pbase = (size_t)img * HH * WPAD + j0 + q;
#pragma unroll
        for (int m = 0; m < 16; m++) {
            int h = c + 16 * m;
            if (h < HH) g_P[pbase + (size_t)h * WPAD] = A[h * 17 + q];
        }
    }
}

// Stage 3: per output row: registers loaded straight from global with
// Hermitian mirror, inverse FFT-512, write real part of 509 samples.
__global__ void __launch_bounds__(256) stage3_kernel(float* __restrict__ out) {
    __shared__ __align__(16) float2 sm[4][SROW];
    int t = threadIdx.x & 63;
    int r = threadIdx.x >> 6;
    int row = blockIdx.x * 4 + r;
    size_t ibase = (size_t)row * WPAD;
    float2 x[8];
#pragma unroll
    for (int a = 0; a < 8; a++) {
        int n = a * 64 + t;
        if (n <= 256) {
            x[a] = g_P[ibase + n];
        } else {
            float2 v = g_P[ibase + 512 - n];
            x[a] = make_float2(v.x, -v.y);
        }
    }
    fft512_core<-1>(x, sm[r], t, r >> 1);
    size_t obase = (size_t)row * WW;
#pragma unroll
    for (int q2 = 0; q2 < 8; q2++) {
        int n = q2 * 64 + t;
        if (n < WW) out[obase + n] = x[q2].x;
    }
}

extern "C" void kernel_launch(void* const* d_in, const int* in_sizes, int n_in,
                              void* d_out, int out_size) {
    const float* u  = (const float*)d_in[0];
    const float* kk = (const float*)d_in[1];
    float* out = (float*)d_out;

    cudaFuncSetAttribute(stage2_kernel,
                         cudaFuncAttributeMaxDynamicSharedMemorySize, 67584);

    init_tw_kernel<<<1, 512>>>();
    stage1_kernel<<<16064, 256>>>(u, kk);            // 64256 rows / 4
    stage2_kernel<<<dim3(17, IMGS), 256, 67584>>>(); // 17 col-tiles x 256 images
    stage3_kernel<<<16064, 256>>>(out);
}

// round 6
// speedup vs baseline: 1.7746x; 1.1663x over previous
#include <cuda_runtime.h>
#include <cuda_fp16.h>

// y = irfft2(rfft2(pad(u)) * rfft2(pad(k)), ortho) cropped.
// (4,64,251,509) fp32 -> 256 images 251x509, pad to 256x512.
// Pack z = u + i*k; with Z2 = FFT2(z):
//   P = U2*K2 = -0.25i*(Z2[ky,kx]^2 - conj(Z2[-ky,-kx])^2)
// conj(Z2[-ky,-kx]) = FFT_col(conj(Z[h,-kx])) -- conj-on-load, no gather.
// Combined ortho scale 2^-25.5 folded into the product.
// fp16 intermediates (tolerance 1e-3): g_Zh raw, g_Ph pre-scaled 2^6,
// T2 pre-scaled 2^12; all descaled exactly (powers of two).

#define IMGS 256
#define HH   251
#define WW   509
#define NJ   257
#define ZP   516   // half2 row stride of Z scratch
#define WPAD 260   // half2 row stride of product scratch
#define EX1S 10    // exchange-1 thread-major stride (16B aligned, conflict-free)
#define P512B 66   // exchange-2 m2-stride (conflict-free both sides)
#define SROW 656   // smem float2 for fft512 (>= 64*10)

__device__ __half2 g_Zh[IMGS * HH * ZP];   // packed row spectra (fp16)
__device__ __half2 g_Ph[IMGS * HH * WPAD]; // product half-spectrum (fp16, x64)
__device__ float2  g_tw[512];              // tw[r] = exp(-2*pi*i*r/512)

__global__ void init_tw_kernel() {
    int r = threadIdx.x;
    double ang = -2.0 * 3.141592653589793238462643383279502884 * (double)r / 512.0;
    g_tw[r] = make_float2((float)cos(ang), (float)sin(ang));
}

__device__ __forceinline__ float2 cmul(float2 a, float2 b) {
    return make_float2(a.x*b.x - a.y*b.y, a.x*b.y + a.y*b.x);
}
__device__ __forceinline__ float2 cadd(float2 a, float2 b) { return make_float2(a.x+b.x, a.y+b.y); }
__device__ __forceinline__ float2 csub(float2 a, float2 b) { return make_float2(a.x-b.x, a.y-b.y); }
template<int DIR>
__device__ __forceinline__ float2 mulmi(float2 v) {   // * (-i) fwd, * (+i) inv
    return (DIR == 1) ? make_float2(v.y, -v.x) : make_float2(-v.y, v.x);
}

template<int DIR>
__device__ __forceinline__ void dft8(float2 x[8]) {
    const float C = 0.70710678118654752f;
    float2 t0 = cadd(x[0], x[4]), t4 = csub(x[0], x[4]);
    float2 t1 = cadd(x[1], x[5]), t5 = csub(x[1], x[5]);
    float2 t2 = cadd(x[2], x[6]), t6 = csub(x[2], x[6]);
    float2 t3 = cadd(x[3], x[7]), t7 = csub(x[3], x[7]);
    t5 = cmul(t5, make_float2(C, -DIR * C));
    t6 = mulmi<DIR>(t6);
    t7 = cmul(t7, make_float2(-C, -DIR * C));
    float2 p0 = cadd(t0, t2), q0 = csub(t0, t2);
    float2 p1 = cadd(t1, t3), q1 = mulmi<DIR>(csub(t1, t3));
    x[0] = cadd(p0, p1); x[4] = csub(p0, p1);
    x[2] = cadd(q0, q1); x[6] = csub(q0, q1);
    float2 r0 = cadd(t4, t6), s0 = csub(t4, t6);
    float2 r1 = cadd(t5, t7), s1 = mulmi<DIR>(csub(t5, t7));
    x[1] = cadd(r0, r1); x[5] = csub(r0, r1);
    x[3] = cadd(s0, s1); x[7] = csub(s0, s1);
}

template<int DIR>
__device__ __forceinline__ void dft16(float2 x[16]) {
    float2 y[16];
#pragma unroll
    for (int b = 0; b < 4; b++) {
        float2 a0 = x[b], a1 = x[b + 4], a2 = x[b + 8], a3 = x[b + 12];
        float2 t0 = cadd(a0, a2), t1 = csub(a0, a2);
        float2 t2 = cadd(a1, a3), t3 = mulmi<DIR>(csub(a1, a3));
        y[b*4 + 0] = cadd(t0, t2);
        y[b*4 + 1] = cadd(t1, t3);
        y[b*4 + 2] = csub(t0, t2);
        y[b*4 + 3] = csub(t1, t3);
    }
    const float c1 = 0.9238795325112867f, s1 = 0.3826834323650898f;
    const float C = 0.70710678118654752f;
    const float2 w1 = make_float2(c1, -DIR * s1);
    const float2 w2 = make_float2(C, -DIR * C);
    const float2 w3 = make_float2(s1, -DIR * c1);
    const float2 w4 = make_float2(0.f, (float)(-DIR));
    const float2 w6 = make_float2(-C, -DIR * C);
    const float2 w9 = make_float2(-c1, DIR * s1);
    y[5]  = cmul(y[5],  w1); y[6]  = cmul(y[6],  w2); y[7]  = cmul(y[7],  w3);
    y[9]  = cmul(y[9],  w2); y[10] = cmul(y[10], w4); y[11] = cmul(y[11], w6);
    y[13] = cmul(y[13], w3); y[14] = cmul(y[14], w6); y[15] = cmul(y[15], w9);
#pragma unroll
    for (int k1 = 0; k1 < 4; k1++) {
        float2 a0 = y[k1], a1 = y[4 + k1], a2 = y[8 + k1], a3 = y[12 + k1];
        float2 t0 = cadd(a0, a2), t1 = csub(a0, a2);
        float2 t2 = cadd(a1, a3), t3 = mulmi<DIR>(csub(a1, a3));
        x[0*4 + k1] = cadd(t0, t2);
        x[1*4 + k1] = cadd(t1, t3);
        x[2*4 + k1] = csub(t0, t2);
        x[3*4 + k1] = csub(t1, t3);
    }
}

// FFT-512: 64-thread block, x[n1] = x[n1*64+t] entry, x[q2] = X[q2*64+t] exit.
// Exchange-1 stores float4-vectorized; all smem phases conflict-free.
// One row per block -> plain __syncthreads (2 warps, fast path).
template<int DIR>
__device__ __forceinline__ void fft512_core(float2 x[8], float2* s, int t) {
    dft8<DIR>(x);
    float2 w = g_tw[t];
    if (DIR < 0) w.y = -w.y;
    float2 cw = w;
#pragma unroll
    for (int k1 = 1; k1 < 8; k1++) { x[k1] = cmul(x[k1], cw); cw = cmul(cw, w); }
    {
        float4* s4 = reinterpret_cast<float4*>(s + (size_t)t * EX1S);
        s4[0] = make_float4(x[0].x, x[0].y, x[1].x, x[1].y);
        s4[1] = make_float4(x[2].x, x[2].y, x[3].x, x[3].y);
        s4[2] = make_float4(x[4].x, x[4].y, x[5].x, x[5].y);
        s4[3] = make_float4(x[6].x, x[6].y, x[7].x, x[7].y);
    }
    __syncthreads();
    int k1 = t >> 3, m2 = t & 7;
#pragma unroll
    for (int m1 = 0; m1 < 8; m1++) x[m1] = s[(m1 * 8 + m2) * EX1S + k1];
    __syncthreads();
    dft8<DIR>(x);
    w = g_tw[8 * m2];
    if (DIR < 0) w.y = -w.y;
    cw = w;
#pragma unroll
    for (int q1 = 1; q1 < 8; q1++) { x[q1] = cmul(x[q1], cw); cw = cmul(cw, w); }
#pragma unroll
    for (int q1 = 0; q1 < 8; q1++) s[m2 * P512B + q1 * 8 + k1] = x[q1];
    __syncthreads();
    int k1c = t & 7, q1c = t >> 3;
#pragma unroll
    for (int m = 0; m < 8; m++) x[m] = s[m * P512B + q1c * 8 + k1c];
    __syncthreads();
    dft8<DIR>(x);   // output: X[q2*64 + q1c*8 + k1c] = X[q2*64 + t]
}

// FFT-256: 16 threads/column (role q), column c. Entry x[n1]=x[n1*16+q],
// exit x[k2]=X[k2*16+q]. Exchange region per-half-warp -> __syncwarp only.
template<int DIR>
__device__ __forceinline__ void fft256_core(float2 x[16], float2* E, int c, int q) {
    dft16<DIR>(x);
    float2 w = g_tw[2 * q];
    if (DIR < 0) w.y = -w.y;
    float2 cw = w;
#pragma unroll
    for (int k1 = 1; k1 < 16; k1++) { x[k1] = cmul(x[k1], cw); cw = cmul(cw, w); }
#pragma unroll
    for (int k1 = 0; k1 < 16; k1++) E[c * 272 + k1 * 17 + q] = x[k1];
    __syncwarp();
#pragma unroll
    for (int n2 = 0; n2 < 16; n2++) x[n2] = E[c * 272 + q * 17 + n2];
    __syncwarp();
    dft16<DIR>(x);
}

// Stage 1: one row per 64-thread block: pack z=u+ik, FFT-512, store fp16.
__global__ void __launch_bounds__(64) stage1_kernel(const float* __restrict__ u,
                                                    const float* __restrict__ kin) {
    __shared__ __align__(16) float2 sm[SROW];
    int t = threadIdx.x;
    int row = blockIdx.x;               // img*251 + h
    size_t ibase = (size_t)row * WW;
    float2 x[8];
#pragma unroll
    for (int a = 0; a < 8; a++) {
        int n = a * 64 + t;
        float ur = 0.f, kr = 0.f;
        if (n < WW) { ur = u[ibase + n]; kr = kin[ibase + n]; }
        x[a] = make_float2(ur, kr);
    }
    fft512_core<1>(x, sm, t);
    size_t obase = (size_t)row * ZP;
#pragma unroll
    for (int q2 = 0; q2 < 8; q2++)
        g_Zh[obase + q2 * 64 + t] = __float22half2_rn(x[q2]);
}

// Stage 2: per (image, 16-col tile):
//   fwd FFT-256 of conj(mirror cols) -> Bbar; T2h = (4096*CS)*i*Bbar^2 (fp16)
//   fwd FFT-256 of primary cols -> A2
//   x = (64*CS)*(-i)*A2^2 + T2h/64 ; inverse FFT-256 ; store fp16 (x64 scale).
__global__ void __launch_bounds__(256, 2) stage2_kernel() {
    extern __shared__ char dsmc[];
    float2*  A   = reinterpret_cast<float2*>(dsmc);            // 4352 f2 = 34816B
    __half2* T2h = reinterpret_cast<__half2*>(dsmc + 34816);   // 4096 h2 = 16384B
    const int t = threadIdx.x;
    const int c = t >> 4;
    const int q = t & 15;
    const int img = blockIdx.y;
    const int j0  = blockIdx.x * 16;
    const size_t zbase = (size_t)img * HH * ZP;
    const float CS   = 0.25f * 2.1073424255447017e-08f;  // 0.25 * 2^-25.5
    const float T2S  = CS * 4096.0f;                      // T2 pre-scale
    const float CS2  = CS * 64.0f;                        // product pre-scale
    const float T2D  = 1.0f / 64.0f;                      // 64/4096
    float2 x[16];

    // ---- mirror tile, conjugated on load ----
    int jm = (512 - (j0 + q)) & 511;
#pragma unroll
    for (int m = 0; m < 16; m++) {
        int h = c + 16 * m;
        float2 v = make_float2(0.f, 0.f);
        if (h < HH) v = __half22float2(g_Zh[zbase + (size_t)h * ZP + jm]);
        A[h * 17 + q] = make_float2(v.x, -v.y);
    }
    __syncthreads();
#pragma unroll
    for (int n1 = 0; n1 < 16; n1++) x[n1] = A[(n1 * 16 + q) * 17 + c];
    __syncthreads();
    fft256_core<1>(x, A, c, q);          // x[k2] = Bbar

    // T2h = T2S * i * Bbar^2  (same thread writes & reads -> no block sync)
#pragma unroll
    for (int k2 = 0; k2 < 16; k2++) {
        float2 pr = cmul(x[k2], x[k2]);
        T2h[c * 256 + k2 * 16 + q] =
            __float22half2_rn(make_float2(-T2S * pr.y, T2S * pr.x));
    }
    __syncthreads();   // protects A reuse (exchange reads done block-wide)

    // ---- primary tile ----
#pragma unroll
    for (int m = 0; m < 16; m++) {
        int h = c + 16 * m;
        float2 v = make_float2(0.f, 0.f);
        if (h < HH) v = __half22float2(g_Zh[zbase + (size_t)h * ZP + j0 + q]);
        A[h * 17 + q] = v;
    }
    __syncthreads();
#pragma unroll
    for (int n1 = 0; n1 < 16; n1++) x[n1] = A[(n1 * 16 + q) * 17 + c];
    __syncthreads();
    fft256_core<1>(x, A, c, q);          // x[k2] = A2

    // ---- product (x64 pre-scale for fp16 storage) ----
#pragma unroll
    for (int k2 = 0; k2 < 16; k2++) {
        float2 pr = cmul(x[k2], x[k2]);
        float2 t2 = __half22float2(T2h[c * 256 + k2 * 16 + q]);
        x[k2] = make_float2(CS2 * pr.y + t2.x * T2D,
                            -CS2 * pr.x + t2.y * T2D);
    }

    // ---- inverse column FFT ----
    fft256_core<-1>(x, A, c, q);

    // ---- stage out (coalesced fp16 half-spectrum writes) ----
    __syncthreads();
#pragma unroll
    for (int k2 = 0; k2 < 16; k2++) A[(k2 * 16 + q) * 17 + c] = x[k2];
    __syncthreads();
    if (j0 + q < NJ) {
        size_t pbase = (size_t)img * HH * WPAD + j0 + q;
#pragma unroll
        for (int m = 0; m < 16; m++) {
            int h = c + 16 * m;
            if (h < HH)
                g_Ph[pbase + (size_t)h * WPAD] = __float22half2_rn(A[h * 17 + q]);
        }
    }
}

// Stage 3: one row per 64-thread block: Hermitian-mirrored fp16 loads,
// inverse FFT-512, write real part descaled by 2^-6.
__global__ void __launch_bounds__(64) stage3_kernel(float* __restrict__ out) {
    __shared__ __align__(16) float2 sm[SROW];
    int t = threadIdx.x;
    int row = blockIdx.x;
    size_t ibase = (size_t)row * WPAD;
    float2 x[8];
#pragma unroll
    for (int a = 0; a < 8; a++) {
        int n = a * 64 + t;
        if (n <= 256) {
            x[a] = __half22float2(g_Ph[ibase + n]);
        } else {
            float2 v = __half22float2(g_Ph[ibase + 512 - n]);
            x[a] = make_float2(v.x, -v.y);
        }
    }
    fft512_core<-1>(x, sm, t);
    size_t obase = (size_t)row * WW;
    const float OD = 1.0f / 64.0f;
#pragma unroll
    for (int q2 = 0; q2 < 8; q2++) {
        int n = q2 * 64 + t;
        if (n < WW) out[obase + n] = x[q2].x * OD;
    }
}

extern "C" void kernel_launch(void* const* d_in, const int* in_sizes, int n_in,
                              void* d_out, int out_size) {
    const float* u  = (const float*)d_in[0];
    const float* kk = (const float*)d_in[1];
    float* out = (float*)d_out;

    cudaFuncSetAttribute(stage2_kernel,
                         cudaFuncAttributeMaxDynamicSharedMemorySize, 51200);

    init_tw_kernel<<<1, 512>>>();
    stage1_kernel<<<IMGS * HH, 64>>>(u, kk);         // 64256 rows
    stage2_kernel<<<dim3(17, IMGS), 256, 51200>>>(); // 17 col-tiles x 256 images
    stage3_kernel<<<IMGS * HH, 64>>>(out);
}

// round 7
// speedup vs baseline: 1.7943x; 1.0111x over previous
#include <cuda_runtime.h>
#include <cuda_fp16.h>

// y = irfft2(rfft2(pad(u)) * rfft2(pad(k)), ortho) cropped.
// (4,64,251,509) fp32 -> 256 images 251x509, pad to 256x512.
// Pack z = u + i*k; with Z2 = FFT2(z):
//   P = U2*K2 = -0.25i*(Z2[ky,kx]^2 - conj(Z2[-ky,-kx])^2)
// conj(Z2[-ky,-kx]) = FFT_col(conj(Z[h,-kx])) -- conj-on-load, no gather.
// Combined ortho scale 2^-25.5 folded into the product.
// fp16 intermediates (tol 1e-3): g_Zh raw, g_Ph pre-scaled 2^6, T2 2^12.
// Stage2 smem staging kept in raw half2 (no extra rounding points).

#define IMGS 256
#define HH   251
#define WW   509
#define NJ   257
#define ZP   516   // half2 row stride of Z scratch
#define WPAD 260   // half2 row stride of product scratch
#define EX1S 10    // fft512 exchange-1 stride (16B aligned, conflict-free)
#define P512B 66   // fft512 exchange-2 stride (conflict-free both sides)
#define SROW 656   // smem float2 for fft512 (>= 64*10)
#define E2S  18    // fft256 exchange per-thread stride (float2)
#define E2C  288   // fft256 exchange per-column stride (float2) = 16*18

__device__ __half2 g_Zh[IMGS * HH * ZP];   // packed row spectra (fp16)
__device__ __half2 g_Ph[IMGS * HH * WPAD]; // product half-spectrum (fp16, x64)
__device__ float2  g_tw[512];              // tw[r] = exp(-2*pi*i*r/512)

__global__ void init_tw_kernel() {
    int r = threadIdx.x;
    double ang = -2.0 * 3.141592653589793238462643383279502884 * (double)r / 512.0;
    g_tw[r] = make_float2((float)cos(ang), (float)sin(ang));
}

__device__ __forceinline__ float2 cmul(float2 a, float2 b) {
    return make_float2(a.x*b.x - a.y*b.y, a.x*b.y + a.y*b.x);
}
__device__ __forceinline__ float2 cadd(float2 a, float2 b) { return make_float2(a.x+b.x, a.y+b.y); }
__device__ __forceinline__ float2 csub(float2 a, float2 b) { return make_float2(a.x-b.x, a.y-b.y); }
template<int DIR>
__device__ __forceinline__ float2 mulmi(float2 v) {   // * (-i) fwd, * (+i) inv
    return (DIR == 1) ? make_float2(v.y, -v.x) : make_float2(-v.y, v.x);
}

template<int DIR>
__device__ __forceinline__ void dft8(float2 x[8]) {
    const float C = 0.70710678118654752f;
    float2 t0 = cadd(x[0], x[4]), t4 = csub(x[0], x[4]);
    float2 t1 = cadd(x[1], x[5]), t5 = csub(x[1], x[5]);
    float2 t2 = cadd(x[2], x[6]), t6 = csub(x[2], x[6]);
    float2 t3 = cadd(x[3], x[7]), t7 = csub(x[3], x[7]);
    t5 = cmul(t5, make_float2(C, -DIR * C));
    t6 = mulmi<DIR>(t6);
    t7 = cmul(t7, make_float2(-C, -DIR * C));
    float2 p0 = cadd(t0, t2), q0 = csub(t0, t2);
    float2 p1 = cadd(t1, t3), q1 = mulmi<DIR>(csub(t1, t3));
    x[0] = cadd(p0, p1); x[4] = csub(p0, p1);
    x[2] = cadd(q0, q1); x[6] = csub(q0, q1);
    float2 r0 = cadd(t4, t6), s0 = csub(t4, t6);
    float2 r1 = cadd(t5, t7), s1 = mulmi<DIR>(csub(t5, t7));
    x[1] = cadd(r0, r1); x[5] = csub(r0, r1);
    x[3] = cadd(s0, s1); x[7] = csub(s0, s1);
}

template<int DIR>
__device__ __forceinline__ void dft16(float2 x[16]) {
    float2 y[16];
#pragma unroll
    for (int b = 0; b < 4; b++) {
        float2 a0 = x[b], a1 = x[b + 4], a2 = x[b + 8], a3 = x[b + 12];
        float2 t0 = cadd(a0, a2), t1 = csub(a0, a2);
        float2 t2 = cadd(a1, a3), t3 = mulmi<DIR>(csub(a1, a3));
        y[b*4 + 0] = cadd(t0, t2);
        y[b*4 + 1] = cadd(t1, t3);
        y[b*4 + 2] = csub(t0, t2);
        y[b*4 + 3] = csub(t1, t3);
    }
    const float c1 = 0.9238795325112867f, s1 = 0.3826834323650898f;
    const float C = 0.70710678118654752f;
    const float2 w1 = make_float2(c1, -DIR * s1);
    const float2 w2 = make_float2(C, -DIR * C);
    const float2 w3 = make_float2(s1, -DIR * c1);
    const float2 w4 = make_float2(0.f, (float)(-DIR));
    const float2 w6 = make_float2(-C, -DIR * C);
    const float2 w9 = make_float2(-c1, DIR * s1);
    y[5]  = cmul(y[5],  w1); y[6]  = cmul(y[6],  w2); y[7]  = cmul(y[7],  w3);
    y[9]  = cmul(y[9],  w2); y[10] = cmul(y[10], w4); y[11] = cmul(y[11], w6);
    y[13] = cmul(y[13], w3); y[14] = cmul(y[14], w6); y[15] = cmul(y[15], w9);
#pragma unroll
    for (int k1 = 0; k1 < 4; k1++) {
        float2 a0 = y[k1], a1 = y[4 + k1], a2 = y[8 + k1], a3 = y[12 + k1];
        float2 t0 = cadd(a0, a2), t1 = csub(a0, a2);
        float2 t2 = cadd(a1, a3), t3 = mulmi<DIR>(csub(a1, a3));
        x[0*4 + k1] = cadd(t0, t2);
        x[1*4 + k1] = cadd(t1, t3);
        x[2*4 + k1] = csub(t0, t2);
        x[3*4 + k1] = csub(t1, t3);
    }
}

// FFT-512: 64-thread block, x[n1] = x[n1*64+t] entry, x[q2] = X[q2*64+t] exit.
template<int DIR>
__device__ __forceinline__ void fft512_core(float2 x[8], float2* s, int t) {
    dft8<DIR>(x);
    float2 w = g_tw[t];
    if (DIR < 0) w.y = -w.y;
    float2 cw = w;
#pragma unroll
    for (int k1 = 1; k1 < 8; k1++) { x[k1] = cmul(x[k1], cw); cw = cmul(cw, w); }
    {
        float4* s4 = reinterpret_cast<float4*>(s + (size_t)t * EX1S);
        s4[0] = make_float4(x[0].x, x[0].y, x[1].x, x[1].y);
        s4[1] = make_float4(x[2].x, x[2].y, x[3].x, x[3].y);
        s4[2] = make_float4(x[4].x, x[4].y, x[5].x, x[5].y);
        s4[3] = make_float4(x[6].x, x[6].y, x[7].x, x[7].y);
    }
    __syncthreads();
    int k1 = t >> 3, m2 = t & 7;
#pragma unroll
    for (int m1 = 0; m1 < 8; m1++) x[m1] = s[(m1 * 8 + m2) * EX1S + k1];
    __syncthreads();
    dft8<DIR>(x);
    w = g_tw[8 * m2];
    if (DIR < 0) w.y = -w.y;
    cw = w;
#pragma unroll
    for (int q1 = 1; q1 < 8; q1++) { x[q1] = cmul(x[q1], cw); cw = cmul(cw, w); }
#pragma unroll
    for (int q1 = 0; q1 < 8; q1++) s[m2 * P512B + q1 * 8 + k1] = x[q1];
    __syncthreads();
    int k1c = t & 7, q1c = t >> 3;
#pragma unroll
    for (int m = 0; m < 8; m++) x[m] = s[m * P512B + q1c * 8 + k1c];
    __syncthreads();
    dft8<DIR>(x);   // output: X[q2*64 + q1c*8 + k1c] = X[q2*64 + t]
}

// FFT-256: 16 threads/column (role q), column c. Entry x[n1]=x[n1*16+q],
// exit x[k2]=X[k2*16+q]. Exchange: contiguous per-thread stores (8 STS.128,
// base 16B-aligned), stride-E2S reads (128B/phase, conflict-free).
template<int DIR>
__device__ __forceinline__ void fft256_core(float2 x[16], float2* E, int c, int q) {
    dft16<DIR>(x);
    float2 w = g_tw[2 * q];
    if (DIR < 0) w.y = -w.y;
    float2 cw = w;
#pragma unroll
    for (int k1 = 1; k1 < 16; k1++) { x[k1] = cmul(x[k1], cw); cw = cmul(cw, w); }
    {
        float4* e4 = reinterpret_cast<float4*>(E + c * E2C + q * E2S);
#pragma unroll
        for (int p = 0; p < 8; p++)
            e4[p] = make_float4(x[2*p].x, x[2*p].y, x[2*p+1].x, x[2*p+1].y);
    }
    __syncwarp();
#pragma unroll
    for (int n2 = 0; n2 < 16; n2++) x[n2] = E[c * E2C + n2 * E2S + q];
    __syncwarp();
    dft16<DIR>(x);
}

// Stage 1: one row per 64-thread block: pack z=u+ik, FFT-512, store fp16.
__global__ void __launch_bounds__(64) stage1_kernel(const float* __restrict__ u,
                                                    const float* __restrict__ kin) {
    __shared__ __align__(16) float2 sm[SROW];
    int t = threadIdx.x;
    int row = blockIdx.x;               // img*251 + h
    size_t ibase = (size_t)row * WW;
    float2 x[8];
#pragma unroll
    for (int a = 0; a < 8; a++) {
        int n = a * 64 + t;
        float ur = 0.f, kr = 0.f;
        if (n < WW) { ur = u[ibase + n]; kr = kin[ibase + n]; }
        x[a] = make_float2(ur, kr);
    }
    fft512_core<1>(x, sm, t);
    size_t obase = (size_t)row * ZP;
#pragma unroll
    for (int q2 = 0; q2 < 8; q2++)
        g_Zh[obase + q2 * 64 + t] = __float22half2_rn(x[q2]);
}

// Stage 2: per (image, 16-col tile):
//   fwd FFT-256 of conj(mirror cols) -> Bbar; T2h = (4096*CS)*i*Bbar^2 (fp16)
//   fwd FFT-256 of primary cols -> A2
//   x = (64*CS)*(-i)*A2^2 + T2h/64 ; inverse FFT-256 ; store fp16 (x64 scale).
// Staging tiles held as raw half2 (no extra rounding); exchange in fp32.
__global__ void __launch_bounds__(256, 2) stage2_kernel() {
    extern __shared__ char dsmc[];
    float2*  E   = reinterpret_cast<float2*>(dsmc);            // 4608 f2 = 36864B
    __half2* Ah  = reinterpret_cast<__half2*>(dsmc);           // staging view (17408B)
    __half2* T2h = reinterpret_cast<__half2*>(dsmc + 36864);   // 4096 h2 = 16384B
    const int t = threadIdx.x;
    const int c = t >> 4;
    const int q = t & 15;
    const int img = blockIdx.y;
    const int j0  = blockIdx.x * 16;
    const size_t zbase = (size_t)img * HH * ZP;
    const float CS   = 0.25f * 2.1073424255447017e-08f;  // 0.25 * 2^-25.5
    const float T2S  = CS * 4096.0f;                      // T2 pre-scale
    const float CS2  = CS * 64.0f;                        // product pre-scale
    const float T2D  = 1.0f / 64.0f;                      // 64/4096
    const __half2 hz = __float22half2_rn(make_float2(0.f, 0.f));
    float2 x[16];

    // ---- stage mirror tile (raw half2), conj applied after convert ----
    int jm = (512 - (j0 + q)) & 511;
#pragma unroll
    for (int m = 0; m < 16; m++) {
        int h = c + 16 * m;
        Ah[h * 17 + q] = (h < HH) ? g_Zh[zbase + (size_t)h * ZP + jm] : hz;
    }
    __syncthreads();
#pragma unroll
    for (int n1 = 0; n1 < 16; n1++) {
        float2 v = __half22float2(Ah[(n1 * 16 + q) * 17 + c]);
        x[n1] = make_float2(v.x, -v.y);
    }
    __syncthreads();
    fft256_core<1>(x, E, c, q);          // x[k2] = Bbar

    // T2h = T2S * i * Bbar^2  (same thread writes & reads)
#pragma unroll
    for (int k2 = 0; k2 < 16; k2++) {
        float2 pr = cmul(x[k2], x[k2]);
        T2h[c * 256 + k2 * 16 + q] =
            __float22half2_rn(make_float2(-T2S * pr.y, T2S * pr.x));
    }
    __syncthreads();   // A region reuse barrier

    // ---- stage primary tile (raw half2) ----
#pragma unroll
    for (int m = 0; m < 16; m++) {
        int h = c + 16 * m;
        Ah[h * 17 + q] = (h < HH) ? g_Zh[zbase + (size_t)h * ZP + j0 + q] : hz;
    }
    __syncthreads();
#pragma unroll
    for (int n1 = 0; n1 < 16; n1++)
        x[n1] = __half22float2(Ah[(n1 * 16 + q) * 17 + c]);
    __syncthreads();
    fft256_core<1>(x, E, c, q);          // x[k2] = A2

    // ---- product (x64 pre-scale for fp16 storage) ----
#pragma unroll
    for (int k2 = 0; k2 < 16; k2++) {
        float2 pr = cmul(x[k2], x[k2]);
        float2 t2 = __half22float2(T2h[c * 256 + k2 * 16 + q]);
        x[k2] = make_float2(CS2 * pr.y + t2.x * T2D,
                            -CS2 * pr.x + t2.y * T2D);
    }

    // ---- inverse column FFT ----
    fft256_core<-1>(x, E, c, q);

    // ---- stage out in half2 (conversion = the g_Ph rounding point) ----
    __syncthreads();
#pragma unroll
    for (int k2 = 0; k2 < 16; k2++)
        Ah[(k2 * 16 + q) * 17 + c] = __float22half2_rn(x[k2]);
    __syncthreads();
    if (j0 + q < NJ) {
        size_t pbase = (size_t)img * HH * WPAD + j0 + q;
#pragma unroll
        for (int m = 0; m < 16; m++) {
            int h = c + 16 * m;
            if (h < HH) g_Ph[pbase + (size_t)h * WPAD] = Ah[h * 17 + q];
        }
    }
}

// Stage 3: one row per 64-thread block: Hermitian-mirrored fp16 loads,
// inverse FFT-512, write real part descaled by 2^-6.
__global__ void __launch_bounds__(64) stage3_kernel(float* __restrict__ out) {
    __shared__ __align__(16) float2 sm[SROW];
    int t = threadIdx.x;
    int row = blockIdx.x;
    size_t ibase = (size_t)row * WPAD;
    float2 x[8];
#pragma unroll
    for (int a = 0; a < 8; a++) {
        int n = a * 64 + t;
        if (n <= 256) {
            x[a] = __half22float2(g_Ph[ibase + n]);
        } else {
            float2 v = __half22float2(g_Ph[ibase + 512 - n]);
            x[a] = make_float2(v.x, -v.y);
        }
    }
    fft512_core<-1>(x, sm, t);
    size_t obase = (size_t)row * WW;
    const float OD = 1.0f / 64.0f;
#pragma unroll
    for (int q2 = 0; q2 < 8; q2++) {
        int n = q2 * 64 + t;
        if (n < WW) out[obase + n] = x[q2].x * OD;
    }
}

extern "C" void kernel_launch(void* const* d_in, const int* in_sizes, int n_in,
                              void* d_out, int out_size) {
    const float* u  = (const float*)d_in[0];
    const float* kk = (const float*)d_in[1];
    float* out = (float*)d_out;

    cudaFuncSetAttribute(stage2_kernel,
                         cudaFuncAttributeMaxDynamicSharedMemorySize, 53248);

    init_tw_kernel<<<1, 512>>>();
    stage1_kernel<<<IMGS * HH, 64>>>(u, kk);         // 64256 rows
    stage2_kernel<<<dim3(17, IMGS), 256, 53248>>>(); // 17 col-tiles x 256 images
    stage3_kernel<<<IMGS * HH, 64>>>(out);
}

// round 8
// speedup vs baseline: 1.9000x; 1.0589x over previous
#include <cuda_runtime.h>
#include <cuda_fp16.h>

// y = irfft2(rfft2(pad(u)) * rfft2(pad(k)), ortho) cropped.
// (4,64,251,509) fp32 -> 256 images 251x509, pad to 256x512.
// Pack z = u + i*k; with Z2 = FFT2(z):
//   P = U2*K2 = -0.25i*(Z2[ky,kx]^2 - conj(Z2[-ky,-kx])^2)
// conj(Z2[-ky,-kx]) = FFT_col(conj(Z[h,-kx])) -- conj-on-load, no gather.
// Combined ortho scale 2^-25.5 folded into the product.
// fp16 intermediates (tol 1e-3): g_Zh raw, g_Ph pre-scaled 2^6, T2 2^12.
// Stage3 pairs two rows per inverse FFT-512 (y1 = Re, y2 = Im): exact.

#define IMGS 256
#define HH   251
#define WW   509
#define NJ   257
#define ZP   516   // half2 row stride of Z scratch
#define WPAD 260   // half2 row stride of product scratch
#define EX1S 10    // fft512 exchange-1 stride (16B aligned, conflict-free)
#define P512B 66   // fft512 exchange-2 stride (conflict-free both sides)
#define SROW 656   // smem float2 for fft512 (>= 64*10)
#define E2S  18    // fft256 exchange per-thread stride (float2)
#define E2C  288   // fft256 exchange per-column stride (float2) = 16*18

__device__ __half2 g_Zh[IMGS * HH * ZP];   // packed row spectra (fp16)
__device__ __half2 g_Ph[IMGS * HH * WPAD]; // product half-spectrum (fp16, x64)
__device__ float2  g_tw[512];              // tw[r] = exp(-2*pi*i*r/512)

__global__ void init_tw_kernel() {
    int r = threadIdx.x;
    double ang = -2.0 * 3.141592653589793238462643383279502884 * (double)r / 512.0;
    g_tw[r] = make_float2((float)cos(ang), (float)sin(ang));
}

__device__ __forceinline__ float2 cmul(float2 a, float2 b) {
    return make_float2(a.x*b.x - a.y*b.y, a.x*b.y + a.y*b.x);
}
__device__ __forceinline__ float2 cadd(float2 a, float2 b) { return make_float2(a.x+b.x, a.y+b.y); }
__device__ __forceinline__ float2 csub(float2 a, float2 b) { return make_float2(a.x-b.x, a.y-b.y); }
template<int DIR>
__device__ __forceinline__ float2 mulmi(float2 v) {   // * (-i) fwd, * (+i) inv
    return (DIR == 1) ? make_float2(v.y, -v.x) : make_float2(-v.y, v.x);
}

template<int DIR>
__device__ __forceinline__ void dft8(float2 x[8]) {
    const float C = 0.70710678118654752f;
    float2 t0 = cadd(x[0], x[4]), t4 = csub(x[0], x[4]);
    float2 t1 = cadd(x[1], x[5]), t5 = csub(x[1], x[5]);
    float2 t2 = cadd(x[2], x[6]), t6 = csub(x[2], x[6]);
    float2 t3 = cadd(x[3], x[7]), t7 = csub(x[3], x[7]);
    t5 = cmul(t5, make_float2(C, -DIR * C));
    t6 = mulmi<DIR>(t6);
    t7 = cmul(t7, make_float2(-C, -DIR * C));
    float2 p0 = cadd(t0, t2), q0 = csub(t0, t2);
    float2 p1 = cadd(t1, t3), q1 = mulmi<DIR>(csub(t1, t3));
    x[0] = cadd(p0, p1); x[4] = csub(p0, p1);
    x[2] = cadd(q0, q1); x[6] = csub(q0, q1);
    float2 r0 = cadd(t4, t6), s0 = csub(t4, t6);
    float2 r1 = cadd(t5, t7), s1 = mulmi<DIR>(csub(t5, t7));
    x[1] = cadd(r0, r1); x[5] = csub(r0, r1);
    x[3] = cadd(s0, s1); x[7] = csub(s0, s1);
}

template<int DIR>
__device__ __forceinline__ void dft16(float2 x[16]) {
    float2 y[16];
#pragma unroll
    for (int b = 0; b < 4; b++) {
        float2 a0 = x[b], a1 = x[b + 4], a2 = x[b + 8], a3 = x[b + 12];
        float2 t0 = cadd(a0, a2), t1 = csub(a0, a2);
        float2 t2 = cadd(a1, a3), t3 = mulmi<DIR>(csub(a1, a3));
        y[b*4 + 0] = cadd(t0, t2);
        y[b*4 + 1] = cadd(t1, t3);
        y[b*4 + 2] = csub(t0, t2);
        y[b*4 + 3] = csub(t1, t3);
    }
    const float c1 = 0.9238795325112867f, s1 = 0.3826834323650898f;
    const float C = 0.70710678118654752f;
    const float2 w1 = make_float2(c1, -DIR * s1);
    const float2 w2 = make_float2(C, -DIR * C);
    const float2 w3 = make_float2(s1, -DIR * c1);
    const float2 w4 = make_float2(0.f, (float)(-DIR));
    const float2 w6 = make_float2(-C, -DIR * C);
    const float2 w9 = make_float2(-c1, DIR * s1);
    y[5]  = cmul(y[5],  w1); y[6]  = cmul(y[6],  w2); y[7]  = cmul(y[7],  w3);
    y[9]  = cmul(y[9],  w2); y[10] = cmul(y[10], w4); y[11] = cmul(y[11], w6);
    y[13] = cmul(y[13], w3); y[14] = cmul(y[14], w6); y[15] = cmul(y[15], w9);
#pragma unroll
    for (int k1 = 0; k1 < 4; k1++) {
        float2 a0 = y[k1], a1 = y[4 + k1], a2 = y[8 + k1], a3 = y[12 + k1];
        float2 t0 = cadd(a0, a2), t1 = csub(a0, a2);
        float2 t2 = cadd(a1, a3), t3 = mulmi<DIR>(csub(a1, a3));
        x[0*4 + k1] = cadd(t0, t2);
        x[1*4 + k1] = cadd(t1, t3);
        x[2*4 + k1] = csub(t0, t2);
        x[3*4 + k1] = csub(t1, t3);
    }
}

// FFT-512: 64-thread block, x[n1] = x[n1*64+t] entry, x[q2] = X[q2*64+t] exit.
template<int DIR>
__device__ __forceinline__ void fft512_core(float2 x[8], float2* s, int t) {
    dft8<DIR>(x);
    float2 w = g_tw[t];
    if (DIR < 0) w.y = -w.y;
    float2 cw = w;
#pragma unroll
    for (int k1 = 1; k1 < 8; k1++) { x[k1] = cmul(x[k1], cw); cw = cmul(cw, w); }
    {
        float4* s4 = reinterpret_cast<float4*>(s + (size_t)t * EX1S);
        s4[0] = make_float4(x[0].x, x[0].y, x[1].x, x[1].y);
        s4[1] = make_float4(x[2].x, x[2].y, x[3].x, x[3].y);
        s4[2] = make_float4(x[4].x, x[4].y, x[5].x, x[5].y);
        s4[3] = make_float4(x[6].x, x[6].y, x[7].x, x[7].y);
    }
    __syncthreads();
    int k1 = t >> 3, m2 = t & 7;
#pragma unroll
    for (int m1 = 0; m1 < 8; m1++) x[m1] = s[(m1 * 8 + m2) * EX1S + k1];
    __syncthreads();
    dft8<DIR>(x);
    w = g_tw[8 * m2];
    if (DIR < 0) w.y = -w.y;
    cw = w;
#pragma unroll
    for (int q1 = 1; q1 < 8; q1++) { x[q1] = cmul(x[q1], cw); cw = cmul(cw, w); }
#pragma unroll
    for (int q1 = 0; q1 < 8; q1++) s[m2 * P512B + q1 * 8 + k1] = x[q1];
    __syncthreads();
    int k1c = t & 7, q1c = t >> 3;
#pragma unroll
    for (int m = 0; m < 8; m++) x[m] = s[m * P512B + q1c * 8 + k1c];
    __syncthreads();
    dft8<DIR>(x);   // output: X[q2*64 + q1c*8 + k1c] = X[q2*64 + t]
}

// FFT-256: 16 threads/column (role q), column c. Entry x[n1]=x[n1*16+q],
// exit x[k2]=X[k2*16+q]. Exchange region is warp-private -> __syncwarp only.
template<int DIR>
__device__ __forceinline__ void fft256_core(float2 x[16], float2* E, int c, int q) {
    dft16<DIR>(x);
    float2 w = g_tw[2 * q];
    if (DIR < 0) w.y = -w.y;
    float2 cw = w;
#pragma unroll
    for (int k1 = 1; k1 < 16; k1++) { x[k1] = cmul(x[k1], cw); cw = cmul(cw, w); }
    {
        float4* e4 = reinterpret_cast<float4*>(E + c * E2C + q * E2S);
#pragma unroll
        for (int p = 0; p < 8; p++)
            e4[p] = make_float4(x[2*p].x, x[2*p].y, x[2*p+1].x, x[2*p+1].y);
    }
    __syncwarp();
#pragma unroll
    for (int n2 = 0; n2 < 16; n2++) x[n2] = E[c * E2C + n2 * E2S + q];
    __syncwarp();
    dft16<DIR>(x);
}

// Stage 1: one row per 64-thread block: pack z=u+ik, FFT-512, store fp16.
__global__ void __launch_bounds__(64) stage1_kernel(const float* __restrict__ u,
                                                    const float* __restrict__ kin) {
    __shared__ __align__(16) float2 sm[SROW];
    int t = threadIdx.x;
    int row = blockIdx.x;               // img*251 + h
    size_t ibase = (size_t)row * WW;
    float2 x[8];
#pragma unroll
    for (int a = 0; a < 8; a++) {
        int n = a * 64 + t;
        float ur = 0.f, kr = 0.f;
        if (n < WW) { ur = u[ibase + n]; kr = kin[ibase + n]; }
        x[a] = make_float2(ur, kr);
    }
    fft512_core<1>(x, sm, t);
    size_t obase = (size_t)row * ZP;
#pragma unroll
    for (int q2 = 0; q2 < 8; q2++)
        g_Zh[obase + q2 * 64 + t] = __float22half2_rn(x[q2]);
}

// Stage 2: per (image, 16-col tile). Dedicated smem regions (no aliasing):
//   E (exchange, warp-private use), T2h, Mstage (mirror tile / out tile),
//   Pstage (primary tile). Both tiles' global loads issue up-front (MLP 32);
//   only 3 block-wide syncs.
__global__ void __launch_bounds__(256, 2) stage2_kernel() {
    extern __shared__ char dsmc[];
    float2*  E   = reinterpret_cast<float2*>(dsmc);            // 36864 B
    __half2* T2h = reinterpret_cast<__half2*>(dsmc + 36864);   // 16384 B
    __half2* Ms  = reinterpret_cast<__half2*>(dsmc + 53248);   // 17408 B
    __half2* Ps  = reinterpret_cast<__half2*>(dsmc + 70656);   // 17408 B
    const int t = threadIdx.x;
    const int c = t >> 4;
    const int q = t & 15;
    const int img = blockIdx.y;
    const int j0  = blockIdx.x * 16;
    const size_t zbase = (size_t)img * HH * ZP;
    const float CS   = 0.25f * 2.1073424255447017e-08f;  // 0.25 * 2^-25.5
    const float T2S  = CS * 4096.0f;                      // T2 pre-scale
    const float CS2  = CS * 64.0f;                        // product pre-scale
    const float T2D  = 1.0f / 64.0f;                      // 64/4096
    const __half2 hz = __float22half2_rn(make_float2(0.f, 0.f));
    float2 x[16];

    // ---- stage BOTH tiles (raw half2), loads issued back-to-back ----
    int jm = (512 - (j0 + q)) & 511;
#pragma unroll
    for (int m = 0; m < 16; m++) {
        int h = c + 16 * m;
        Ms[h * 17 + q] = (h < HH) ? g_Zh[zbase + (size_t)h * ZP + jm] : hz;
        Ps[h * 17 + q] = (h < HH) ? g_Zh[zbase + (size_t)h * ZP + j0 + q] : hz;
    }
    __syncthreads();   // sync #1: staging complete

    // ---- mirror FFT (conj applied at transposed read) ----
#pragma unroll
    for (int n1 = 0; n1 < 16; n1++) {
        float2 v = __half22float2(Ms[(n1 * 16 + q) * 17 + c]);
        x[n1] = make_float2(v.x, -v.y);
    }
    fft256_core<1>(x, E, c, q);          // x[k2] = Bbar

    // T2h = T2S * i * Bbar^2  (same thread writes & reads later)
#pragma unroll
    for (int k2 = 0; k2 < 16; k2++) {
        float2 pr = cmul(x[k2], x[k2]);
        T2h[c * 256 + k2 * 16 + q] =
            __float22half2_rn(make_float2(-T2S * pr.y, T2S * pr.x));
    }

    // ---- primary FFT (Pstage stable since sync #1) ----
#pragma unroll
    for (int n1 = 0; n1 < 16; n1++)
        x[n1] = __half22float2(Ps[(n1 * 16 + q) * 17 + c]);
    fft256_core<1>(x, E, c, q);          // x[k2] = A2

    // ---- product (x64 pre-scale for fp16 storage) ----
#pragma unroll
    for (int k2 = 0; k2 < 16; k2++) {
        float2 pr = cmul(x[k2], x[k2]);
        float2 t2 = __half22float2(T2h[c * 256 + k2 * 16 + q]);
        x[k2] = make_float2(CS2 * pr.y + t2.x * T2D,
                            -CS2 * pr.x + t2.y * T2D);
    }

    // ---- inverse column FFT ----
    fft256_core<-1>(x, E, c, q);

    // ---- stage out in half2 into Ms (all warps done reading Ms) ----
    __syncthreads();   // sync #2: lagging warps finish Ms transposed reads
#pragma unroll
    for (int k2 = 0; k2 < 16; k2++)
        Ms[(k2 * 16 + q) * 17 + c] = __float22half2_rn(x[k2]);
    __syncthreads();   // sync #3: out tile complete
    if (j0 + q < NJ) {
        size_t pbase = (size_t)img * HH * WPAD + j0 + q;
#pragma unroll
        for (int m = 0; m < 16; m++) {
            int h = c + 16 * m;
            if (h < HH) g_Ph[pbase + (size_t)h * WPAD] = Ms[h * 17 + q];
        }
    }
}

// Stage 3: TWO rows per 64-thread block. x = P1ext + i*P2ext, one inverse
// FFT-512, y1 = Re -> row0, y2 = Im -> row1. Exact (linearity).
__global__ void __launch_bounds__(64) stage3_kernel(float* __restrict__ out) {
    __shared__ __align__(16) float2 sm[SROW];
    int t = threadIdx.x;
    int row0 = blockIdx.x * 2;
    size_t ib1 = (size_t)row0 * WPAD;
    size_t ib2 = ib1 + WPAD;
    float2 x[8];
#pragma unroll
    for (int a = 0; a < 8; a++) {
        int n = a * 64 + t;
        float2 p1, p2;
        if (n <= 256) {
            p1 = __half22float2(g_Ph[ib1 + n]);
            p2 = __half22float2(g_Ph[ib2 + n]);
        } else {
            float2 v1 = __half22float2(g_Ph[ib1 + 512 - n]);
            float2 v2 = __half22float2(g_Ph[ib2 + 512 - n]);
            p1 = make_float2(v1.x, -v1.y);
            p2 = make_float2(v2.x, -v2.y);
        }
        x[a] = make_float2(p1.x - p2.y, p1.y + p2.x);
    }
    fft512_core<-1>(x, sm, t);
    size_t ob1 = (size_t)row0 * WW;
    size_t ob2 = ob1 + WW;
    const float OD = 1.0f / 64.0f;
#pragma unroll
    for (int q2 = 0; q2 < 8; q2++) {
        int n = q2 * 64 + t;
        if (n < WW) {
            out[ob1 + n] = x[q2].x * OD;
            out[ob2 + n] = x[q2].y * OD;
        }
    }
}

extern "C" void kernel_launch(void* const* d_in, const int* in_sizes, int n_in,
                              void* d_out, int out_size) {
    const float* u  = (const float*)d_in[0];
    const float* kk = (const float*)d_in[1];
    float* out = (float*)d_out;

    cudaFuncSetAttribute(stage2_kernel,
                         cudaFuncAttributeMaxDynamicSharedMemorySize, 88064);

    init_tw_kernel<<<1, 512>>>();
    stage1_kernel<<<IMGS * HH, 64>>>(u, kk);         // 64256 rows
    stage2_kernel<<<dim3(17, IMGS), 256, 88064>>>(); // 17 col-tiles x 256 images
    stage3_kernel<<<IMGS * HH / 2, 64>>>(out);       // 32128 row-pairs
}